// round 11
// baseline (speedup 1.0000x reference)
#include <cuda_runtime.h>
#include <cuda_fp16.h>
#include <cstdint>
#include <cstddef>

#define T_STEPS 512
#define BATCH   64
#define HID     1024
#define G4      4096
#define M1      (T_STEPS * BATCH)   // 32768
#define NCTA    128

// ---------------- device scratch (no allocs allowed) ----------------
__device__ float    g_xpre[(size_t)M1 * G4];      // 512 MB: [T*B, 4H]
__device__ __half   g_hbuf[2][BATCH * HID];       // double-buffered h, fp16 A-fragment-major
__device__ unsigned g_cnt1[16];                   // tree barrier: 16 groups of 8 CTAs
__device__ unsigned g_cnt2;                       // tree barrier root
__device__ unsigned g_gen;                        // monotonic generation

// ---------------- helpers ----------------
// fp16 MMA, fp32 accumulate: D[16x8] += A[16x16] x B[16x8]
__device__ __forceinline__ void mma_f16(float* c, const uint32_t* a, const uint32_t* b) {
    asm volatile(
        "mma.sync.aligned.m16n8k16.row.col.f32.f16.f16.f32 "
        "{%0,%1,%2,%3}, {%4,%5,%6,%7}, {%8,%9}, {%0,%1,%2,%3};"
        : "+f"(c[0]), "+f"(c[1]), "+f"(c[2]), "+f"(c[3])
        : "r"(a[0]), "r"(a[1]), "r"(a[2]), "r"(a[3]), "r"(b[0]), "r"(b[1]));
}

__device__ __forceinline__ void cp_async16(uint32_t saddr, const void* gaddr) {
    asm volatile("cp.async.cg.shared.global [%0], [%1], 16;\n"
                 :: "r"(saddr), "l"(gaddr));
}
#define CP_COMMIT() asm volatile("cp.async.commit_group;\n" ::: "memory")
#define CP_WAIT1()  asm volatile("cp.async.wait_group 1;\n" ::: "memory")

__device__ __forceinline__ uint32_t h2bits(float a, float b) {
    __half2 h = __floats2half2_rn(a, b);
    return *(uint32_t*)&h;
}

// ---------------- phase 1: x_pre = input @ W_ih^T + b_ih + b_hh (fp16 mma) ----------------
// CTA tile 128x128, 8 warps in 4(M) x 2(N), warp tile 32x64. K-chunk 16 (one m16n8k16 slab),
// 2-stage smem pipeline. As/Bs rows: 8 half2 words, stride 12 (conflict-free fragment reads).
__global__ __launch_bounds__(256) void gemm1_k(
    const float* __restrict__ A, const float* __restrict__ W,
    const float* __restrict__ bih, const float* __restrict__ bhh) {
    __shared__ uint32_t As[2][128][12];
    __shared__ uint32_t Bs[2][128][12];

    const int tid   = threadIdx.x;
    const int lane  = tid & 31;
    const int wid   = tid >> 5;
    const int warpM = wid & 3;
    const int warpN = wid >> 2;
    const int m0 = blockIdx.y * 128;
    const int n0 = blockIdx.x * 128;

    const int r1 = tid >> 2;          // loader row 0..63 (also +64)
    const int r2 = r1 + 64;
    const int c4 = (tid & 3) * 4;     // float col
    const int h2c = (tid & 3) * 2;    // half2 word col

    float acc[2][8][4];
#pragma unroll
    for (int mt = 0; mt < 2; mt++)
#pragma unroll
        for (int nt = 0; nt < 8; nt++)
#pragma unroll
            for (int r = 0; r < 4; r++) acc[mt][nt][r] = 0.0f;

    const float* Ap1 = A + (size_t)(m0 + r1) * 1024 + c4;
    const float* Ap2 = A + (size_t)(m0 + r2) * 1024 + c4;
    const float* Wp1 = W + (size_t)(n0 + r1) * 1024 + c4;
    const float* Wp2 = W + (size_t)(n0 + r2) * 1024 + c4;

    const int g  = lane >> 2;
    const int tg = lane & 3;

    float4 ra1, ra2, rb1, rb2;
    ra1 = *(const float4*)(Ap1);
    ra2 = *(const float4*)(Ap2);
    rb1 = *(const float4*)(Wp1);
    rb2 = *(const float4*)(Wp2);
    {
        uint2 u;
        u.x = h2bits(ra1.x, ra1.y); u.y = h2bits(ra1.z, ra1.w);
        *(uint2*)&As[0][r1][h2c] = u;
        u.x = h2bits(ra2.x, ra2.y); u.y = h2bits(ra2.z, ra2.w);
        *(uint2*)&As[0][r2][h2c] = u;
        u.x = h2bits(rb1.x, rb1.y); u.y = h2bits(rb1.z, rb1.w);
        *(uint2*)&Bs[0][r1][h2c] = u;
        u.x = h2bits(rb2.x, rb2.y); u.y = h2bits(rb2.z, rb2.w);
        *(uint2*)&Bs[0][r2][h2c] = u;
    }
    __syncthreads();

    for (int k = 0; k < 64; k++) {
        if (k < 63) {
            const int off = (k + 1) * 16;
            ra1 = *(const float4*)(Ap1 + off);
            ra2 = *(const float4*)(Ap2 + off);
            rb1 = *(const float4*)(Wp1 + off);
            rb2 = *(const float4*)(Wp2 + off);
        }
        const int cur = k & 1;

        // fragments: a = (g,2tg|2tg+1)(col tg), (g+8,..), (g,2tg+8|+9)(col tg+4), (g+8,..)
        uint32_t af[2][4];
#pragma unroll
        for (int mt = 0; mt < 2; mt++) {
            const int mb = warpM * 32 + mt * 16;
            af[mt][0] = As[cur][mb + g][tg];
            af[mt][1] = As[cur][mb + 8 + g][tg];
            af[mt][2] = As[cur][mb + g][tg + 4];
            af[mt][3] = As[cur][mb + 8 + g][tg + 4];
        }
#pragma unroll
        for (int nt = 0; nt < 8; nt++) {
            const int nb = warpN * 64 + nt * 8;
            uint32_t bf[2];
            bf[0] = Bs[cur][nb + g][tg];
            bf[1] = Bs[cur][nb + g][tg + 4];
            mma_f16(acc[0][nt], af[0], bf);
            mma_f16(acc[1][nt], af[1], bf);
        }
        __syncthreads();
        if (k < 63) {
            const int nxt = cur ^ 1;
            uint2 u;
            u.x = h2bits(ra1.x, ra1.y); u.y = h2bits(ra1.z, ra1.w);
            *(uint2*)&As[nxt][r1][h2c] = u;
            u.x = h2bits(ra2.x, ra2.y); u.y = h2bits(ra2.z, ra2.w);
            *(uint2*)&As[nxt][r2][h2c] = u;
            u.x = h2bits(rb1.x, rb1.y); u.y = h2bits(rb1.z, rb1.w);
            *(uint2*)&Bs[nxt][r1][h2c] = u;
            u.x = h2bits(rb2.x, rb2.y); u.y = h2bits(rb2.z, rb2.w);
            *(uint2*)&Bs[nxt][r2][h2c] = u;
            __syncthreads();
        }
    }

#pragma unroll
    for (int nt = 0; nt < 8; nt++) {
        const int col = n0 + warpN * 64 + nt * 8 + 2 * tg;
        const float bias0 = bih[col] + bhh[col];
        const float bias1 = bih[col + 1] + bhh[col + 1];
#pragma unroll
        for (int mt = 0; mt < 2; mt++) {
            const int row = m0 + warpM * 32 + mt * 16 + g;
            float2 v0; v0.x = acc[mt][nt][0] + bias0; v0.y = acc[mt][nt][1] + bias1;
            *(float2*)&g_xpre[(size_t)row * G4 + col] = v0;
            float2 v1; v1.x = acc[mt][nt][2] + bias0; v1.y = acc[mt][nt][3] + bias1;
            *(float2*)&g_xpre[(size_t)(row + 8) * G4 + col] = v1;
        }
    }
}

// ---------------- grid-wide barrier: two-level tree, self-resetting ----------------
__device__ __forceinline__ void gbar(int cta) {
    __syncthreads();
    if (threadIdx.x == 0) {
        volatile unsigned* vgen = &g_gen;
        const unsigned gen0 = *vgen;
        __threadfence();
        const int grp = cta >> 3;
        if (atomicAdd(&g_cnt1[grp], 1u) == 7u) {
            g_cnt1[grp] = 0u;
            __threadfence();
            if (atomicAdd(&g_cnt2, 1u) == 15u) {
                g_cnt2 = 0u;
                __threadfence();
                *vgen = gen0 + 1u;
            } else {
                while (*vgen == gen0) { __nanosleep(16); }
            }
        } else {
            while (*vgen == gen0) { __nanosleep(16); }
        }
    }
    __syncthreads();
}

// ---------------- fp16 A-fragment addressing ----------------
// h element (b,k): byte offset = ((mt*64+ks)*32 + lane)*16 + j*4 + half*2
//   mt=b>>4, ks=k>>4, lane=(b&7)*4+((k>>1)&3), j=((k>>3)&1)*2+((b>>3)&1), half=k&1
__device__ __forceinline__ uint32_t hfrag_off(int b, int k) {
    return (uint32_t)((((b >> 4) * 64 + (k >> 4)) * 32 + (b & 7) * 4 + ((k >> 1) & 3)) * 16
                      + (((k >> 3) & 1) * 2 + ((b >> 3) & 1)) * 4 + (k & 1) * 2);
}

// ---------------- phase 2: persistent recurrence (fp16 mma, 8 K-eighths x 2 m-pairs) ----------------
// 128 CTAs x 512 threads (16 warps). CTA owns 32 gate-cols {g*1024 + cta*8 + u}.
// K = 64 k16-blocks. Warp w: kh=w>>1 owns ks in [kh*8, kh*8+8); mtp=w&1 owns m-tiles
// {2mtp, 2mtp+1}. A staged via cp.async ring-2 (2 KB chunks, 4 chunks/warp/step).
// 8 partial buffers reduced in the gate phase (1 cell per thread).
#define PRE_STRIDE 34
#define PRE_BUF    (64 * PRE_STRIDE)
__global__ __launch_bounds__(512) void lstm_rec_k(
    const float* __restrict__ Whh, const float* __restrict__ h0,
    const float* __restrict__ c0, float* __restrict__ out) {
    extern __shared__ uint32_t smem[];
    uint32_t* W_s   = smem;                          // 16384 u32 (64 KB) fp16 b-fragments
    float*    pre_s = (float*)(smem + 16384);        // 8 x [64][34] = 69632 B
    uint32_t* hs    = smem + 16384 + 8 * PRE_BUF;    // 16 warps x 2 x 2KB = 64 KB

    const int tid    = threadIdx.x;
    const int lane   = tid & 31;
    const int w      = tid >> 5;                     // 0..15
    const int kh     = w >> 1;                       // K eighth (0..7)
    const int mtp    = w & 1;                        // m-pair (0..1)
    const int cta    = blockIdx.x;
    const int hcbase = cta * 8;

    const uint32_t hs_w = (uint32_t)__cvta_generic_to_shared(hs) + w * 4096 + lane * 16;

    // ---- fill W b-fragments (one-time), fp16 ----
    for (int e = tid; e < 8192; e += 512) {
        const int li = e & 31;
        const int ks = (e >> 5) & 63;
        const int nt = e >> 11;
        const int g  = li >> 2;
        const int tg = li & 3;
        const float* wr = Whh + (size_t)(nt * HID + hcbase + g) * HID + ks * 16 + 2 * tg;
        W_s[e * 2]     = h2bits(__ldg(wr),     __ldg(wr + 1));
        W_s[e * 2 + 1] = h2bits(__ldg(wr + 8), __ldg(wr + 9));
    }

    // ---- cell ownership: thread owns exactly one cell (b, u) ----
    const int u = tid & 7;
    const int b = tid >> 3;                          // 0..63

    float c_r, h_r;
    {
        const int idx = b * HID + hcbase + u;
        c_r = c0[idx];
        h_r = h0[idx];
        *(__half*)((char*)g_hbuf[0] + hfrag_off(b, hcbase + u)) = __float2half_rn(h_r);
    }

    gbar(cta);

    const int ks0 = kh * 8;

    for (int t = 0; t < T_STEPS; t++) {
        const char*  hin = (const char*)g_hbuf[t & 1];
        __half*     hout = g_hbuf[(t + 1) & 1];

        // ---- prefetch x_pre (independent of h; hidden under mma) ----
        float xpv[4];
        {
            const float* xb = g_xpre + (size_t)t * BATCH * G4 + (size_t)b * G4 + hcbase + u;
            xpv[0] = __ldg(xb);
            xpv[1] = __ldg(xb + HID);
            xpv[2] = __ldg(xb + 2 * HID);
            xpv[3] = __ldg(xb + 3 * HID);
        }

        float acc[2][4][4];                          // [mtl][n][reg]
#pragma unroll
        for (int m = 0; m < 2; m++)
#pragma unroll
            for (int n = 0; n < 4; n++)
#pragma unroll
                for (int r = 0; r < 4; r++) acc[m][n][r] = 0.0f;

        const char* hb = hin + lane * 16;

        // ring-2: chunk = 2 ks x 2 mtl = 2 KB into slot kc&1; 4 chunks total
        {
            const uint32_t dst = hs_w;               // slot 0
#pragma unroll
            for (int c = 0; c < 2; c++)
#pragma unroll
                for (int mtl = 0; mtl < 2; mtl++)
                    cp_async16(dst + (c * 2 + mtl) * 512,
                               hb + (size_t)(((mtp * 2 + mtl) * 64 + ks0 + c) * 512));
            CP_COMMIT();
        }

#pragma unroll
        for (int kc = 0; kc < 4; kc++) {
            if (kc < 3) {
                const int kc2 = kc + 1;
                const uint32_t dst = hs_w + (kc2 & 1) * 2048;
#pragma unroll
                for (int c = 0; c < 2; c++)
#pragma unroll
                    for (int mtl = 0; mtl < 2; mtl++)
                        cp_async16(dst + (c * 2 + mtl) * 512,
                                   hb + (size_t)(((mtp * 2 + mtl) * 64 + ks0 + kc2 * 2 + c) * 512));
                CP_COMMIT();
                CP_WAIT1();            // chunk kc resident (kc+1 outstanding)
            } else {
                asm volatile("cp.async.wait_group 0;\n" ::: "memory");
            }
            __syncwarp();

            const uint32_t bufb = hs_w + (kc & 1) * 2048;
#pragma unroll
            for (int c = 0; c < 2; c++) {
                const int ksg = ks0 + kc * 2 + c;
                uint32_t af0[4], af1[4];
                asm volatile("ld.shared.v4.b32 {%0,%1,%2,%3}, [%4];"
                             : "=r"(af0[0]), "=r"(af0[1]), "=r"(af0[2]), "=r"(af0[3])
                             : "r"(bufb + (c * 2 + 0) * 512));
                asm volatile("ld.shared.v4.b32 {%0,%1,%2,%3}, [%4];"
                             : "=r"(af1[0]), "=r"(af1[1]), "=r"(af1[2]), "=r"(af1[3])
                             : "r"(bufb + (c * 2 + 1) * 512));
#pragma unroll
                for (int n = 0; n < 4; n++) {
                    const uint2 bv = *(const uint2*)&W_s[((n * 64 + ksg) * 32 + lane) * 2];
                    mma_f16(acc[0][n], af0, (const uint32_t*)&bv);
                    mma_f16(acc[1][n], af1, (const uint32_t*)&bv);
                }
            }
        }

        // publish partials to this K-eighth's buffer (rows disjoint between mtp warps)
        {
            float* pb = pre_s + kh * PRE_BUF;
            const int rg = lane >> 2;
            const int cg = 2 * (lane & 3);
#pragma unroll
            for (int mtl = 0; mtl < 2; mtl++) {
                const int rb = (mtp * 2 + mtl) * 16 + rg;
#pragma unroll
                for (int n = 0; n < 4; n++) {
                    const int colb = n * 8 + cg;
                    float2 v0; v0.x = acc[mtl][n][0]; v0.y = acc[mtl][n][1];
                    *(float2*)&pb[rb * PRE_STRIDE + colb] = v0;
                    float2 v1; v1.x = acc[mtl][n][2]; v1.y = acc[mtl][n][3];
                    *(float2*)&pb[(rb + 8) * PRE_STRIDE + colb] = v1;
                }
            }
        }
        __syncthreads();

        // gate math + h/c update + stores (1 cell per thread); sum 8 partials
        {
            float pi = xpv[0], pf = xpv[1], po = xpv[2], pg = xpv[3];
#pragma unroll
            for (int p = 0; p < 8; p++) {
                const float* pb = &pre_s[p * PRE_BUF + b * PRE_STRIDE];
                pi += pb[u];
                pf += pb[8 + u];
                po += pb[16 + u];
                pg += pb[24 + u];
            }
            const float ig = 1.0f / (1.0f + __expf(-pi));
            const float fg = 1.0f / (1.0f + __expf(-pf));
            const float og = 1.0f / (1.0f + __expf(-po));
            c_r = fg * c_r + ig * tanhf(pg);
            h_r = og * tanhf(c_r);
            *(__half*)((char*)hout + hfrag_off(b, hcbase + u)) = __float2half_rn(h_r);
            out[(size_t)t * BATCH * HID + b * HID + hcbase + u] = h_r;
        }

        gbar(cta);
    }

    // finals: out = [output | h_f | c_f]
    {
        float* hf = out + (size_t)T_STEPS * BATCH * HID;
        float* cf = hf + BATCH * HID;
        hf[b * HID + hcbase + u] = h_r;
        cf[b * HID + hcbase + u] = c_r;
    }
}

// ---------------- launch ----------------
extern "C" void kernel_launch(void* const* d_in, const int* in_sizes, int n_in,
                              void* d_out, int out_size) {
    const float* input = (const float*)d_in[0];   // [T, B, I]
    const float* h0    = (const float*)d_in[1];   // [1, B, H]
    const float* c0    = (const float*)d_in[2];   // [1, B, H]
    const float* W_ih  = (const float*)d_in[3];   // [4H, I]
    const float* b_ih  = (const float*)d_in[4];   // [4H]
    const float* W_hh  = (const float*)d_in[5];   // [4H, H]
    const float* b_hh  = (const float*)d_in[6];   // [4H]
    float* out = (float*)d_out;

    // W_s (65536 B) + pre_s (69632 B) + staging (65536 B) = 200704 B
    const int rec_smem = 65536 + 8 * PRE_BUF * 4 + 65536;
    cudaFuncSetAttribute(lstm_rec_k, cudaFuncAttributeMaxDynamicSharedMemorySize, rec_smem);

    dim3 g1(G4 / 128, M1 / 128);   // (32, 256)
    gemm1_k<<<g1, 256>>>(input, W_ih, b_ih, b_hh);
    lstm_rec_k<<<NCTA, 512, rec_smem>>>(W_hh, h0, c0, out);
}

// round 12
// speedup vs baseline: 1.8436x; 1.8436x over previous
#include <cuda_runtime.h>
#include <cuda_fp16.h>
#include <cstdint>
#include <cstddef>

#define T_STEPS 512
#define BATCH   64
#define HID     1024
#define G4      4096
#define M1      (T_STEPS * BATCH)   // 32768
#define NCTA    128

// ---------------- device scratch (no allocs allowed) ----------------
__device__ float    g_xpre[(size_t)M1 * G4];      // 512 MB: [T*B, 4H]
__device__ __half   g_a16[(size_t)M1 * HID];      // 64 MB: input in fp16
__device__ __half   g_w16[(size_t)G4 * HID];      // 8 MB: W_ih in fp16
__device__ __half   g_hbuf[2][BATCH * HID];       // double-buffered h, fp16 A-fragment-major
__device__ unsigned g_cnt1[16];                   // tree barrier: 16 groups of 8 CTAs
__device__ unsigned g_cnt2;                       // tree barrier root
__device__ unsigned g_gen;                        // monotonic generation

// ---------------- helpers ----------------
__device__ __forceinline__ void mma_f16(float* c, const uint32_t* a, const uint32_t* b) {
    asm volatile(
        "mma.sync.aligned.m16n8k16.row.col.f32.f16.f16.f32 "
        "{%0,%1,%2,%3}, {%4,%5,%6,%7}, {%8,%9}, {%0,%1,%2,%3};"
        : "+f"(c[0]), "+f"(c[1]), "+f"(c[2]), "+f"(c[3])
        : "r"(a[0]), "r"(a[1]), "r"(a[2]), "r"(a[3]), "r"(b[0]), "r"(b[1]));
}

__device__ __forceinline__ void cp_async16(uint32_t saddr, const void* gaddr) {
    asm volatile("cp.async.cg.shared.global [%0], [%1], 16;\n"
                 :: "r"(saddr), "l"(gaddr));
}
#define CP_COMMIT() asm volatile("cp.async.commit_group;\n" ::: "memory")
#define CP_WAIT1()  asm volatile("cp.async.wait_group 1;\n" ::: "memory")
#define CP_WAIT2()  asm volatile("cp.async.wait_group 2;\n" ::: "memory")

__device__ __forceinline__ uint32_t h2bits(float a, float b) {
    __half2 h = __floats2half2_rn(a, b);
    return *(uint32_t*)&h;
}

// ---------------- phase 0: fp32 -> fp16 conversion (input, W_ih) ----------------
__global__ __launch_bounds__(256) void cvt_k(const float* __restrict__ A,
                                             const float* __restrict__ W) {
    const int nthr = gridDim.x * blockDim.x;
    const int tid0 = blockIdx.x * blockDim.x + threadIdx.x;
    // input: 33554432 floats = 8388608 float4
    for (size_t i = tid0; i < (size_t)M1 * HID / 4; i += nthr) {
        float4 v = *(const float4*)(A + i * 4);
        uint2 o; o.x = h2bits(v.x, v.y); o.y = h2bits(v.z, v.w);
        *(uint2*)&g_a16[i * 4] = o;
    }
    // W_ih: 4194304 floats = 1048576 float4
    for (size_t i = tid0; i < (size_t)G4 * HID / 4; i += nthr) {
        float4 v = *(const float4*)(W + i * 4);
        uint2 o; o.x = h2bits(v.x, v.y); o.y = h2bits(v.z, v.w);
        *(uint2*)&g_w16[i * 4] = o;
    }
}

// ---------------- phase 1: x_pre = input @ W_ih^T + b_ih + b_hh (fp16, cp.async ring-3) ----------------
// CTA tile 128x128, 8 warps 4(M) x 2(N), warp tile 32x64. K-chunk 32 halves (2 k16 slabs).
// Stage = 128 rows x 80 B (64 B data + 16 pad) per array; 3 stages; all loads via cp.async.
// Row stride 80 B = 20 words: fragment reads verified bank-conflict-free.
#define G1_STRIDE_W 20
#define G1_STAGE_W  (128 * G1_STRIDE_W)            // words per stage per array
__global__ __launch_bounds__(256, 2) void gemm1_k(
    const float* __restrict__ bih, const float* __restrict__ bhh) {
    extern __shared__ uint32_t sm1[];
    uint32_t* As = sm1;                             // 3 stages x 2560 words
    uint32_t* Bs = sm1 + 3 * G1_STAGE_W;

    const int tid   = threadIdx.x;
    const int lane  = tid & 31;
    const int wid   = tid >> 5;
    const int warpM = wid & 3;
    const int warpN = wid >> 2;
    const int m0 = blockIdx.y * 128;
    const int n0 = blockIdx.x * 128;

    const int g  = lane >> 2;
    const int tg = lane & 3;

    const uint32_t as_b = (uint32_t)__cvta_generic_to_shared(As);
    const uint32_t bs_b = (uint32_t)__cvta_generic_to_shared(Bs);

    // loader: 512 granules (16 B) per array per chunk; thread t -> granules 2t, 2t+1
    const int lr0 = (tid * 2) >> 2;                 // row of granule 0
    const int lg0 = (tid * 2) & 3;                  // gcol of granule 0
    const int lr1 = (tid * 2 + 1) >> 2;
    const int lg1 = (tid * 2 + 1) & 3;
    const char* Asrc0 = (const char*)g_a16 + (size_t)(m0 + lr0) * 2048 + lg0 * 16;
    const char* Asrc1 = (const char*)g_a16 + (size_t)(m0 + lr1) * 2048 + lg1 * 16;
    const char* Wsrc0 = (const char*)g_w16 + (size_t)(n0 + lr0) * 2048 + lg0 * 16;
    const char* Wsrc1 = (const char*)g_w16 + (size_t)(n0 + lr1) * 2048 + lg1 * 16;
    const uint32_t ad0 = as_b + (uint32_t)(lr0 * 80 + lg0 * 16);
    const uint32_t ad1 = as_b + (uint32_t)(lr1 * 80 + lg1 * 16);
    const uint32_t bd0 = bs_b + (uint32_t)(lr0 * 80 + lg0 * 16);
    const uint32_t bd1 = bs_b + (uint32_t)(lr1 * 80 + lg1 * 16);

    float acc[2][8][4];
#pragma unroll
    for (int mt = 0; mt < 2; mt++)
#pragma unroll
        for (int nt = 0; nt < 8; nt++)
#pragma unroll
            for (int r = 0; r < 4; r++) acc[mt][nt][r] = 0.0f;

    // prologue: issue chunks 0, 1
#pragma unroll
    for (int pc = 0; pc < 2; pc++) {
        const uint32_t so = (uint32_t)(pc * G1_STAGE_W * 4);
        cp_async16(ad0 + so, Asrc0 + pc * 64);
        cp_async16(ad1 + so, Asrc1 + pc * 64);
        cp_async16(bd0 + so, Wsrc0 + pc * 64);
        cp_async16(bd1 + so, Wsrc1 + pc * 64);
        CP_COMMIT();
    }

    for (int c = 0; c < 32; c++) {
        CP_WAIT1();                  // chunk c resident
        __syncthreads();             // all warps done with chunk c-1 (slot of c+2)
        if (c + 2 < 32) {
            const uint32_t so = (uint32_t)(((c + 2) % 3) * G1_STAGE_W * 4);
            cp_async16(ad0 + so, Asrc0 + (c + 2) * 64);
            cp_async16(ad1 + so, Asrc1 + (c + 2) * 64);
            cp_async16(bd0 + so, Wsrc0 + (c + 2) * 64);
            cp_async16(bd1 + so, Wsrc1 + (c + 2) * 64);
        }
        CP_COMMIT();

        const uint32_t* Ac = As + (c % 3) * G1_STAGE_W;
        const uint32_t* Bc = Bs + (c % 3) * G1_STAGE_W;
#pragma unroll
        for (int ksl = 0; ksl < 2; ksl++) {
            const int kb = ksl * 8;
            uint32_t af[2][4];
#pragma unroll
            for (int mt = 0; mt < 2; mt++) {
                const int mb = warpM * 32 + mt * 16;
                af[mt][0] = Ac[(mb + g) * G1_STRIDE_W + kb + tg];
                af[mt][1] = Ac[(mb + 8 + g) * G1_STRIDE_W + kb + tg];
                af[mt][2] = Ac[(mb + g) * G1_STRIDE_W + kb + tg + 4];
                af[mt][3] = Ac[(mb + 8 + g) * G1_STRIDE_W + kb + tg + 4];
            }
#pragma unroll
            for (int nt = 0; nt < 8; nt++) {
                const int nb = warpN * 64 + nt * 8;
                uint32_t bf[2];
                bf[0] = Bc[(nb + g) * G1_STRIDE_W + kb + tg];
                bf[1] = Bc[(nb + g) * G1_STRIDE_W + kb + tg + 4];
                mma_f16(acc[0][nt], af[0], bf);
                mma_f16(acc[1][nt], af[1], bf);
            }
        }
    }

#pragma unroll
    for (int nt = 0; nt < 8; nt++) {
        const int col = n0 + warpN * 64 + nt * 8 + 2 * tg;
        const float bias0 = bih[col] + bhh[col];
        const float bias1 = bih[col + 1] + bhh[col + 1];
#pragma unroll
        for (int mt = 0; mt < 2; mt++) {
            const int row = m0 + warpM * 32 + mt * 16 + g;
            float2 v0; v0.x = acc[mt][nt][0] + bias0; v0.y = acc[mt][nt][1] + bias1;
            *(float2*)&g_xpre[(size_t)row * G4 + col] = v0;
            float2 v1; v1.x = acc[mt][nt][2] + bias0; v1.y = acc[mt][nt][3] + bias1;
            *(float2*)&g_xpre[(size_t)(row + 8) * G4 + col] = v1;
        }
    }
}

// ---------------- grid-wide barrier: two-level tree, self-resetting ----------------
__device__ __forceinline__ void gbar(int cta) {
    __syncthreads();
    if (threadIdx.x == 0) {
        volatile unsigned* vgen = &g_gen;
        const unsigned gen0 = *vgen;
        __threadfence();
        const int grp = cta >> 3;
        if (atomicAdd(&g_cnt1[grp], 1u) == 7u) {
            g_cnt1[grp] = 0u;
            __threadfence();
            if (atomicAdd(&g_cnt2, 1u) == 15u) {
                g_cnt2 = 0u;
                __threadfence();
                *vgen = gen0 + 1u;
            } else {
                while (*vgen == gen0) { __nanosleep(16); }
            }
        } else {
            while (*vgen == gen0) { __nanosleep(16); }
        }
    }
    __syncthreads();
}

// ---------------- fp16 A-fragment addressing ----------------
// h element (b,k): byte offset = ((mt*64+ks)*32 + lane)*16 + j*4 + half*2
//   mt=b>>4, ks=k>>4, lane=(b&7)*4+((k>>1)&3), j=((k>>3)&1)*2+((b>>3)&1), half=k&1
__device__ __forceinline__ uint32_t hfrag_off(int b, int k) {
    return (uint32_t)((((b >> 4) * 64 + (k >> 4)) * 32 + (b & 7) * 4 + ((k >> 1) & 3)) * 16
                      + (((k >> 3) & 1) * 2 + ((b >> 3) & 1)) * 4 + (k & 1) * 2);
}

// ---------------- phase 2: persistent recurrence (fp16 mma, 4 K-quarters x 2 m-pairs) ----------------
// R10 winner, verbatim: 128 CTAs x 256 threads (8 warps), cp.async ring-3, 4 partial buffers.
#define PRE_STRIDE 34
#define PRE_BUF    (64 * PRE_STRIDE)
__global__ __launch_bounds__(256) void lstm_rec_k(
    const float* __restrict__ Whh, const float* __restrict__ h0,
    const float* __restrict__ c0, float* __restrict__ out) {
    extern __shared__ uint32_t smem[];
    uint32_t* W_s   = smem;                          // 16384 u32 (64 KB) fp16 b-fragments
    float*    pre_s = (float*)(smem + 16384);        // 4 x [64][34] = 34816 B
    uint32_t* hs    = smem + 16384 + 4 * PRE_BUF;    // 8 warps x 3 x 2KB = 48 KB

    const int tid    = threadIdx.x;
    const int lane   = tid & 31;
    const int w      = tid >> 5;                     // 0..7
    const int kh     = w >> 1;                       // K quarter (0..3)
    const int mtp    = w & 1;                        // m-pair (0..1)
    const int cta    = blockIdx.x;
    const int hcbase = cta * 8;

    const uint32_t hs_w = (uint32_t)__cvta_generic_to_shared(hs) + w * 6144 + lane * 16;

    // ---- fill W b-fragments (one-time), fp16 ----
    for (int e = tid; e < 8192; e += 256) {
        const int li = e & 31;
        const int ks = (e >> 5) & 63;
        const int nt = e >> 11;
        const int g  = li >> 2;
        const int tg = li & 3;
        const float* wr = Whh + (size_t)(nt * HID + hcbase + g) * HID + ks * 16 + 2 * tg;
        W_s[e * 2]     = h2bits(__ldg(wr),     __ldg(wr + 1));
        W_s[e * 2 + 1] = h2bits(__ldg(wr + 8), __ldg(wr + 9));
    }

    // ---- cell ownership: thread owns hcol u, batches {bq2, bq2+32} ----
    const int u   = tid & 7;
    const int bq2 = tid >> 3;                        // 0..31

    float c_r[2], h_r[2];
#pragma unroll
    for (int j = 0; j < 2; j++) {
        const int b   = bq2 + 32 * j;
        const int idx = b * HID + hcbase + u;
        c_r[j] = c0[idx];
        const float h = h0[idx];
        h_r[j] = h;
        *(__half*)((char*)g_hbuf[0] + hfrag_off(b, hcbase + u)) = __float2half_rn(h);
    }

    gbar(cta);

    const int ks0 = kh * 16;

    for (int t = 0; t < T_STEPS; t++) {
        const char*  hin = (const char*)g_hbuf[t & 1];
        __half*     hout = g_hbuf[(t + 1) & 1];

        // ---- prefetch x_pre (independent of h; hidden under mma) ----
        float xpv[2][4];
        {
            const float* xp = g_xpre + (size_t)t * BATCH * G4;
#pragma unroll
            for (int j = 0; j < 2; j++) {
                const float* xb = xp + (size_t)(bq2 + 32 * j) * G4 + hcbase + u;
                xpv[j][0] = __ldg(xb);
                xpv[j][1] = __ldg(xb + HID);
                xpv[j][2] = __ldg(xb + 2 * HID);
                xpv[j][3] = __ldg(xb + 3 * HID);
            }
        }

        float acc[2][4][4];                          // [mtl][n][reg]
#pragma unroll
        for (int m = 0; m < 2; m++)
#pragma unroll
            for (int n = 0; n < 4; n++)
#pragma unroll
                for (int r = 0; r < 4; r++) acc[m][n][r] = 0.0f;

        const char* hb = hin + lane * 16;

        // chunk = 2 ks x 2 mtl = 2 KB into ring slot kc % 3; prologue: chunks 0,1
#pragma unroll
        for (int pc = 0; pc < 2; pc++) {
            const uint32_t dst = hs_w + (pc % 3) * 2048;
#pragma unroll
            for (int c = 0; c < 2; c++)
#pragma unroll
                for (int mtl = 0; mtl < 2; mtl++)
                    cp_async16(dst + (c * 2 + mtl) * 512,
                               hb + (size_t)(((mtp * 2 + mtl) * 64 + ks0 + pc * 2 + c) * 512));
            CP_COMMIT();
        }

#pragma unroll
        for (int kc = 0; kc < 8; kc++) {
            if (kc + 2 < 8) {
                const int kc2 = kc + 2;
                const uint32_t dst = hs_w + (kc2 % 3) * 2048;
#pragma unroll
                for (int c = 0; c < 2; c++)
#pragma unroll
                    for (int mtl = 0; mtl < 2; mtl++)
                        cp_async16(dst + (c * 2 + mtl) * 512,
                                   hb + (size_t)(((mtp * 2 + mtl) * 64 + ks0 + kc2 * 2 + c) * 512));
            }
            CP_COMMIT();
            CP_WAIT2();               // chunk kc resident
            __syncwarp();

            const uint32_t bufb = hs_w + (kc % 3) * 2048;
#pragma unroll
            for (int c = 0; c < 2; c++) {
                const int ksg = ks0 + kc * 2 + c;
                uint32_t af0[4], af1[4];
                asm volatile("ld.shared.v4.b32 {%0,%1,%2,%3}, [%4];"
                             : "=r"(af0[0]), "=r"(af0[1]), "=r"(af0[2]), "=r"(af0[3])
                             : "r"(bufb + (c * 2 + 0) * 512));
                asm volatile("ld.shared.v4.b32 {%0,%1,%2,%3}, [%4];"
                             : "=r"(af1[0]), "=r"(af1[1]), "=r"(af1[2]), "=r"(af1[3])
                             : "r"(bufb + (c * 2 + 1) * 512));
#pragma unroll
                for (int n = 0; n < 4; n++) {
                    const uint2 bv = *(const uint2*)&W_s[((n * 64 + ksg) * 32 + lane) * 2];
                    mma_f16(acc[0][n], af0, (const uint32_t*)&bv);
                    mma_f16(acc[1][n], af1, (const uint32_t*)&bv);
                }
            }
        }

        // publish partials to this K-quarter's buffer (rows disjoint between mtp warps)
        {
            float* pb = pre_s + kh * PRE_BUF;
            const int rg = lane >> 2;
            const int cg = 2 * (lane & 3);
#pragma unroll
            for (int mtl = 0; mtl < 2; mtl++) {
                const int rb = (mtp * 2 + mtl) * 16 + rg;
#pragma unroll
                for (int n = 0; n < 4; n++) {
                    const int colb = n * 8 + cg;
                    float2 v0; v0.x = acc[mtl][n][0]; v0.y = acc[mtl][n][1];
                    *(float2*)&pb[rb * PRE_STRIDE + colb] = v0;
                    float2 v1; v1.x = acc[mtl][n][2]; v1.y = acc[mtl][n][3];
                    *(float2*)&pb[(rb + 8) * PRE_STRIDE + colb] = v1;
                }
            }
        }
        __syncthreads();

        // gate math + h/c update + stores (2 cells per thread); sum 4 partials
        float* orow = out + (size_t)t * BATCH * HID;
#pragma unroll
        for (int j = 0; j < 2; j++) {
            const int b = bq2 + 32 * j;
            float pi = xpv[j][0], pf = xpv[j][1], po = xpv[j][2], pg = xpv[j][3];
#pragma unroll
            for (int p = 0; p < 4; p++) {
                const float* pb = &pre_s[p * PRE_BUF + b * PRE_STRIDE];
                pi += pb[u];
                pf += pb[8 + u];
                po += pb[16 + u];
                pg += pb[24 + u];
            }
            const float ig = 1.0f / (1.0f + __expf(-pi));
            const float fg = 1.0f / (1.0f + __expf(-pf));
            const float og = 1.0f / (1.0f + __expf(-po));
            c_r[j] = fg * c_r[j] + ig * tanhf(pg);
            const float h = og * tanhf(c_r[j]);
            h_r[j] = h;
            *(__half*)((char*)hout + hfrag_off(b, hcbase + u)) = __float2half_rn(h);
            orow[b * HID + hcbase + u] = h;
        }

        gbar(cta);
    }

    // finals: out = [output | h_f | c_f]
    float* hf = out + (size_t)T_STEPS * BATCH * HID;
    float* cf = hf + BATCH * HID;
#pragma unroll
    for (int j = 0; j < 2; j++) {
        const int b = bq2 + 32 * j;
        hf[b * HID + hcbase + u] = h_r[j];
        cf[b * HID + hcbase + u] = c_r[j];
    }
}

// ---------------- launch ----------------
extern "C" void kernel_launch(void* const* d_in, const int* in_sizes, int n_in,
                              void* d_out, int out_size) {
    const float* input = (const float*)d_in[0];   // [T, B, I]
    const float* h0    = (const float*)d_in[1];   // [1, B, H]
    const float* c0    = (const float*)d_in[2];   // [1, B, H]
    const float* W_ih  = (const float*)d_in[3];   // [4H, I]
    const float* b_ih  = (const float*)d_in[4];   // [4H]
    const float* W_hh  = (const float*)d_in[5];   // [4H, H]
    const float* b_hh  = (const float*)d_in[6];   // [4H]
    float* out = (float*)d_out;

    const int g1_smem  = 6 * G1_STAGE_W * 4;            // 61440 B
    const int rec_smem = 65536 + 4 * PRE_BUF * 4 + 49152;  // 149504 B
    cudaFuncSetAttribute(gemm1_k, cudaFuncAttributeMaxDynamicSharedMemorySize, g1_smem);
    cudaFuncSetAttribute(lstm_rec_k, cudaFuncAttributeMaxDynamicSharedMemorySize, rec_smem);

    cvt_k<<<2048, 256>>>(input, W_ih);
    dim3 g1(G4 / 128, M1 / 128);   // (32, 256)
    gemm1_k<<<g1, 256, g1_smem>>>(b_ih, b_hh);
    lstm_rec_k<<<NCTA, 256, rec_smem>>>(W_hh, h0, c0, out);
}